// round 15
// baseline (speedup 1.0000x reference)
#include <cuda_runtime.h>
#include <cuda_fp16.h>
#include <cstdint>
#include <math.h>

#define Bsz 8
#define Cdim 256
#define HW 2304
#define CHW (Cdim*HW)          // 589824
#define BNEPS 1e-5f
#define INV_C (1.0f/256.0f)

// ---- static scratch (allocation-free), all fp16 ----
__device__ __half g_QhL[Bsz*CHW];
__device__ __half g_QhR[Bsz*CHW];
__device__ __half g_KhL[Bsz*CHW];
__device__ __half g_KhR[Bsz*CHW];
__device__ __half g_VhL[Bsz*CHW];
__device__ __half g_VhR[Bsz*CHW];
__device__ float g_WfQ[Cdim*Cdim];
__device__ float g_WfK[Cdim*Cdim];
__device__ float g_bfQ[Cdim];
__device__ float g_bfK[Cdim];

// ============================================================
// helpers
// ============================================================
__device__ __forceinline__ uint32_t smem_u32(const void* p) {
    uint32_t a;
    asm("{ .reg .u64 t; cvta.to.shared.u64 t, %1; cvt.u32.u64 %0, t; }" : "=r"(a) : "l"(p));
    return a;
}
__device__ __forceinline__ void ldsm_x4(uint32_t a, uint32_t& r0, uint32_t& r1, uint32_t& r2, uint32_t& r3) {
    asm volatile("ldmatrix.sync.aligned.m8n8.x4.shared.b16 {%0,%1,%2,%3}, [%4];"
                 : "=r"(r0), "=r"(r1), "=r"(r2), "=r"(r3) : "r"(a));
}
__device__ __forceinline__ void ldsm_x2(uint32_t a, uint32_t& r0, uint32_t& r1) {
    asm volatile("ldmatrix.sync.aligned.m8n8.x2.shared.b16 {%0,%1}, [%2];"
                 : "=r"(r0), "=r"(r1) : "r"(a));
}
__device__ __forceinline__ void ldsm_x2t(uint32_t a, uint32_t& r0, uint32_t& r1) {
    asm volatile("ldmatrix.sync.aligned.m8n8.x2.trans.shared.b16 {%0,%1}, [%2];"
                 : "=r"(r0), "=r"(r1) : "r"(a));
}
__device__ __forceinline__ void mma_f16(float* c, const uint32_t* a, const uint32_t* b) {
    asm volatile("mma.sync.aligned.m16n8k16.row.col.f32.f16.f16.f32 "
                 "{%0,%1,%2,%3}, {%4,%5,%6,%7}, {%8,%9}, {%0,%1,%2,%3};"
                 : "+f"(c[0]), "+f"(c[1]), "+f"(c[2]), "+f"(c[3])
                 : "r"(a[0]), "r"(a[1]), "r"(a[2]), "r"(a[3]), "r"(b[0]), "r"(b[1]));
}
__device__ __forceinline__ uint32_t pack2h(float a, float b) {
    __half2 t = __floats2half2_rn(a, b);
    return *(uint32_t*)&t;
}
#define CP_ASYNC16(dst, src) \
    asm volatile("cp.async.cg.shared.global [%0], [%1], 16;" :: "r"(dst), "l"(src) : "memory")
#define CP_COMMIT() asm volatile("cp.async.commit_group;" ::: "memory")
#define CP_WAIT0()  asm volatile("cp.async.wait_group 0;" ::: "memory")

// ============================================================
// Fold BN into conv1x1
// ============================================================
__global__ void fold_kernel(const float* __restrict__ Wq, const float* __restrict__ bq,
                            const float* __restrict__ gq, const float* __restrict__ betaq,
                            const float* __restrict__ mq, const float* __restrict__ vq,
                            const float* __restrict__ Wk, const float* __restrict__ bk,
                            const float* __restrict__ gk, const float* __restrict__ betak,
                            const float* __restrict__ mk, const float* __restrict__ vk)
{
    int idx = blockIdx.x * blockDim.x + threadIdx.x;
    if (idx >= Cdim * Cdim) return;
    int o = idx >> 8;
    float sq = gq[o] * rsqrtf(vq[o] + BNEPS);
    float sk = gk[o] * rsqrtf(vk[o] + BNEPS);
    g_WfQ[idx] = Wq[idx] * sq;
    g_WfK[idx] = Wk[idx] * sk;
    if ((idx & 255) == 0) {
        g_bfQ[o] = (bq[o] - mq[o]) * sq + betaq[o];
        g_bfK[o] = (bk[o] - mk[o]) * sk + betak[o];
    }
}

// ============================================================
// V convert: fea fp32 -> fp16 scratch (both sides)
// ============================================================
__global__ void vconv_kernel(const float* __restrict__ fleft, const float* __restrict__ fright)
{
    int i = blockIdx.x * blockDim.x + threadIdx.x;      // float4 index
    const int n4 = (Bsz * CHW) / 4;
    if (i >= n4) return;
    float4 a = ((const float4*)fleft)[i];
    float4 b = ((const float4*)fright)[i];
    ((uint2*)g_VhL)[i] = make_uint2(pack2h(a.x, a.y), pack2h(a.z, a.w));
    ((uint2*)g_VhR)[i] = make_uint2(pack2h(b.x, b.y), pack2h(b.z, b.w));
}

// ============================================================
// Projection GEMM via fp16 mma (unchanged)
// ============================================================
#define PJ_WOFF 0
#define PJ_XOFF 67584
#define PJ_SMEM (67584 + 32*272)

__global__ void __launch_bounds__(256, 2)
proj_kernel(const float* __restrict__ fleft, const float* __restrict__ fright)
{
    extern __shared__ char sm[];
    uint32_t sb = smem_u32(sm);
    int tid = threadIdx.x;
    int t = tid & 31, w = tid >> 5;

    int z = blockIdx.z;
    int p = z >> 3, b = z & 7;
    const float* X  = ((p & 1) ? fright : fleft) + b * CHW;
    const float* Wf = (p < 2) ? g_WfQ : g_WfK;
    const float* bf = (p < 2) ? g_bfQ : g_bfK;
    __half* dst =
        ((p == 0) ? g_QhL : (p == 1) ? g_QhR : (p == 2) ? g_KhL : g_KhR) + b * CHW;

    int n0 = blockIdx.x * 128, o0 = blockIdx.y * 128;

    #pragma unroll
    for (int it = 0; it < 32; it++) {
        int idx = tid + it * 256;
        int r = idx >> 6, c4 = idx & 63;
        float4 v = *(const float4*)(Wf + (o0 + r) * 256 + c4 * 4);
        *(uint2*)(sm + PJ_WOFF + r * 528 + c4 * 8) = make_uint2(pack2h(v.x, v.y), pack2h(v.z, v.w));
    }

    float oacc[16][4];
    #pragma unroll
    for (int i = 0; i < 16; i++)
        #pragma unroll
        for (int j = 0; j < 4; j++) oacc[i][j] = 0.0f;

    uint32_t aW = sb + PJ_WOFF + (w * 16 + (t & 7) + ((t >> 3) & 1) * 8) * 528 + (t >> 4) * 16;
    uint32_t bX = sb + PJ_XOFF + (t & 15) * 272;

    #pragma unroll 1
    for (int ch = 0; ch < 8; ch++) {
        __syncthreads();
        #pragma unroll
        for (int it = 0; it < 4; it++) {
            int idx = tid + it * 256;
            int rc = idx >> 5, n4 = idx & 31;
            float4 v = *(const float4*)(X + (ch * 32 + rc) * HW + n0 + n4 * 4);
            *(uint2*)(sm + PJ_XOFF + rc * 272 + n4 * 8) = make_uint2(pack2h(v.x, v.y), pack2h(v.z, v.w));
        }
        __syncthreads();

        #pragma unroll
        for (int ksl = 0; ksl < 2; ksl++) {
            uint32_t a[4];
            ldsm_x4(aW + ch * 64 + ksl * 32, a[0], a[1], a[2], a[3]);
            #pragma unroll
            for (int nt = 0; nt < 16; nt++) {
                uint32_t bb[2];
                ldsm_x2t(bX + ksl * 16 * 272 + nt * 16, bb[0], bb[1]);
                mma_f16(oacc[nt], a, bb);
            }
        }
    }

    int r0 = o0 + w * 16 + (t >> 2);
    float b0 = bf[r0], b1 = bf[r0 + 8];
    #pragma unroll
    for (int nt = 0; nt < 16; nt++) {
        int col = n0 + nt * 8 + (t & 3) * 2;
        *(uint32_t*)(dst + r0 * HW + col)       = pack2h(oacc[nt][0] + b0, oacc[nt][1] + b0);
        *(uint32_t*)(dst + (r0 + 8) * HW + col) = pack2h(oacc[nt][2] + b1, oacc[nt][3] + b1);
    }
}

// ============================================================
// Flash attention, all-fp16, fp32 accum. 2 CTAs/SM for phase overlap.
// 64 q-rows/CTA, 72 key tiles of 32. 128 threads = 4 warps:
// g = w>>1 owns 32 rows (2 A-frags), h = w&1 (16-key half for S, 128-d half for PV).
// smem/CTA (108.3 KB): Qs[64][528B] | Ks[2][32][528B] | Vs[2][32][528B]
//                      | Ps fp16[64][144B] | li[64]
// ============================================================
#define AQOFF 0
#define AKOFF 33792
#define AVOFF 67584
#define APOFF 101376
#define ALOFF 110592
#define ATT_SMEM 110848
#define KVT 16896            // 32*528

__global__ void __launch_bounds__(128, 2)
attn_kernel(float* __restrict__ out)
{
    extern __shared__ char sm[];
    uint32_t sb = smem_u32(sm);
    int tid = threadIdx.x;
    int t = tid & 31, w = tid >> 5;
    int g = w >> 1, h = w & 1;

    int u = blockIdx.y;
    int att = u >> 3, b = u & 7;
    const __half* Q = (att == 0 ? g_QhL : g_QhR) + b * CHW;
    const __half* K = (att == 0 ? g_KhR : g_KhL) + b * CHW;
    const __half* V = (att == 0 ? g_VhR : g_VhL) + b * CHW;
    float* O = out + att * (Bsz * CHW) + b * CHW;
    int q0 = blockIdx.x * 64;

    if (tid < 64) *(float*)(sm + ALOFF + tid * 4) = 0.0f;

    // Q tile via cp.async: 64 rows x 32 chunks of 16B
    #pragma unroll
    for (int it = 0; it < 16; it++) {
        int idx = tid + it * 128;
        int r = idx >> 5, c16 = idx & 31;
        CP_ASYNC16(sb + AQOFF + r * 528 + c16 * 16, (const char*)(Q + (q0 + r) * 256) + c16 * 16);
    }
    // K/V tile 0 into buffer 0 (32 rows x 32 chunks each)
    #pragma unroll
    for (int it = 0; it < 8; it++) {
        int idx = tid + it * 128;
        int r = idx >> 5, c16 = idx & 31;
        CP_ASYNC16(sb + AKOFF + r * 528 + c16 * 16, (const char*)(K + r * 256) + c16 * 16);
        CP_ASYNC16(sb + AVOFF + r * 528 + c16 * 16, (const char*)(V + r * 256) + c16 * 16);
    }
    CP_COMMIT();

    int m0 = g * 32;            // 32-row group (g in {0,1})
    int n0 = h * 16;            // 16-key half (S phase)
    int nd0 = h * 128;          // 128-d half (PV phase)

    uint32_t aQ0 = sb + AQOFF + (m0 + (t & 7) + ((t >> 3) & 1) * 8) * 528 + (t >> 4) * 16;
    uint32_t aQ1 = aQ0 + 16 * 528;
    int r0 = m0 + (t >> 2);
    uint32_t aP0 = sb + APOFF + (m0 + (t & 7) + ((t >> 3) & 1) * 8) * 144 + (t >> 4) * 16;
    uint32_t aP1 = aP0 + 16 * 144;

    float oacc[2][16][4];
    #pragma unroll
    for (int f = 0; f < 2; f++)
        #pragma unroll
        for (int i = 0; i < 16; i++)
            #pragma unroll
            for (int j = 0; j < 4; j++) oacc[f][i][j] = 0.0f;
    float li00 = 0.0f, li01 = 0.0f, li10 = 0.0f, li11 = 0.0f;

    #pragma unroll 1
    for (int kt = 0; kt < 72; kt++) {
        int buf = kt & 1;
        uint32_t kbase = sb + AKOFF + buf * KVT;
        uint32_t vbase = sb + AVOFF + buf * KVT;

        CP_WAIT0();
        __syncthreads();      // tile kt resident; prev iter's K/V/P consumers done

        // prefetch tile kt+1 into other buffer
        if (kt < 71) {
            int k0n = (kt + 1) * 32;
            uint32_t kd = sb + AKOFF + (buf ^ 1) * KVT;
            uint32_t vd = sb + AVOFF + (buf ^ 1) * KVT;
            #pragma unroll
            for (int it = 0; it < 8; it++) {
                int idx = tid + it * 128;
                int r = idx >> 5, c16 = idx & 31;
                CP_ASYNC16(kd + r * 528 + c16 * 16, (const char*)(K + (k0n + r) * 256) + c16 * 16);
                CP_ASYNC16(vd + r * 528 + c16 * 16, (const char*)(V + (k0n + r) * 256) + c16 * 16);
            }
            CP_COMMIT();
        }

        // ---- S = Q K^T (fp16): warp computes S[32 x 16] via 2 A-frags ----
        uint32_t bK = kbase + (n0 + (t & 7)) * 528 + ((t >> 3) & 1) * 16;
        float sacc[2][2][4];
        #pragma unroll
        for (int f = 0; f < 2; f++)
            #pragma unroll
            for (int i = 0; i < 2; i++)
                #pragma unroll
                for (int j = 0; j < 4; j++) sacc[f][i][j] = 0.0f;
        #pragma unroll
        for (int ks = 0; ks < 16; ks++) {
            uint32_t a0[4], a1[4];
            ldsm_x4(aQ0 + ks * 32, a0[0], a0[1], a0[2], a0[3]);
            ldsm_x4(aQ1 + ks * 32, a1[0], a1[1], a1[2], a1[3]);
            #pragma unroll
            for (int nt = 0; nt < 2; nt++) {
                uint32_t bb[2];
                ldsm_x2(bK + nt * 8 * 528 + ks * 32, bb[0], bb[1]);
                mma_f16(sacc[0][nt], a0, bb);
                mma_f16(sacc[1][nt], a1, bb);
            }
        }

        // ---- softmax (no max subtraction) + store P (fp16) ----
        #pragma unroll
        for (int f = 0; f < 2; f++) {
            int rf = r0 + f * 16;
            #pragma unroll
            for (int nt = 0; nt < 2; nt++) {
                float p0 = __expf(sacc[f][nt][0] * INV_C);
                float p1 = __expf(sacc[f][nt][1] * INV_C);
                float p2 = __expf(sacc[f][nt][2] * INV_C);
                float p3 = __expf(sacc[f][nt][3] * INV_C);
                if (f == 0) { li00 += p0 + p1; li01 += p2 + p3; }
                else        { li10 += p0 + p1; li11 += p2 + p3; }
                int col = n0 + nt * 8 + (t & 3) * 2;
                *(uint32_t*)(sm + APOFF + rf * 144 + col * 2)       = pack2h(p0, p1);
                *(uint32_t*)(sm + APOFF + (rf + 8) * 144 + col * 2) = pack2h(p2, p3);
            }
        }
        __syncthreads();   // P complete (4 warps)

        // ---- O += P @ V (fp16): each V B-frag feeds both A-frags ----
        uint32_t bV = vbase + (t & 15) * 528 + nd0 * 2;
        #pragma unroll
        for (int ks = 0; ks < 2; ks++) {
            uint32_t a0[4], a1[4];
            ldsm_x4(aP0 + ks * 32, a0[0], a0[1], a0[2], a0[3]);
            ldsm_x4(aP1 + ks * 32, a1[0], a1[1], a1[2], a1[3]);
            #pragma unroll
            for (int nt = 0; nt < 16; nt++) {
                uint32_t bb[2];
                ldsm_x2t(bV + ks * 16 * 528 + nt * 16, bb[0], bb[1]);
                mma_f16(oacc[0][nt], a0, bb);
                mma_f16(oacc[1][nt], a1, bb);
            }
        }
    }

    // ---- li reduction (4 rows per thread) ----
    li00 += __shfl_xor_sync(0xFFFFFFFFu, li00, 1);
    li00 += __shfl_xor_sync(0xFFFFFFFFu, li00, 2);
    li01 += __shfl_xor_sync(0xFFFFFFFFu, li01, 1);
    li01 += __shfl_xor_sync(0xFFFFFFFFu, li01, 2);
    li10 += __shfl_xor_sync(0xFFFFFFFFu, li10, 1);
    li10 += __shfl_xor_sync(0xFFFFFFFFu, li10, 2);
    li11 += __shfl_xor_sync(0xFFFFFFFFu, li11, 1);
    li11 += __shfl_xor_sync(0xFFFFFFFFu, li11, 2);
    if ((t & 3) == 0) {
        atomicAdd((float*)(sm + ALOFF + r0 * 4), li00);
        atomicAdd((float*)(sm + ALOFF + (r0 + 8) * 4), li01);
        atomicAdd((float*)(sm + ALOFF + (r0 + 16) * 4), li10);
        atomicAdd((float*)(sm + ALOFF + (r0 + 24) * 4), li11);
    }
    __syncthreads();

    // ---- epilogue: O[r][d]/li -> out[d*HW + q0 + r] ----
    float rl00 = 1.0f / *(float*)(sm + ALOFF + r0 * 4);
    float rl01 = 1.0f / *(float*)(sm + ALOFF + (r0 + 8) * 4);
    float rl10 = 1.0f / *(float*)(sm + ALOFF + (r0 + 16) * 4);
    float rl11 = 1.0f / *(float*)(sm + ALOFF + (r0 + 24) * 4);
    #pragma unroll
    for (int nt = 0; nt < 16; nt++) {
        int col = nd0 + nt * 8 + (t & 3) * 2;
        O[col * HW + q0 + r0]            = oacc[0][nt][0] * rl00;
        O[(col + 1) * HW + q0 + r0]      = oacc[0][nt][1] * rl00;
        O[col * HW + q0 + r0 + 8]        = oacc[0][nt][2] * rl01;
        O[(col + 1) * HW + q0 + r0 + 8]  = oacc[0][nt][3] * rl01;
        O[col * HW + q0 + r0 + 16]       = oacc[1][nt][0] * rl10;
        O[(col + 1) * HW + q0 + r0 + 16] = oacc[1][nt][1] * rl10;
        O[col * HW + q0 + r0 + 24]       = oacc[1][nt][2] * rl11;
        O[(col + 1) * HW + q0 + r0 + 24] = oacc[1][nt][3] * rl11;
    }
}

extern "C" void kernel_launch(void* const* d_in, const int* in_sizes, int n_in,
                              void* d_out, int out_size)
{
    const float* fea_left  = (const float*)d_in[0];
    const float* fea_right = (const float*)d_in[1];
    const float* Wq    = (const float*)d_in[2];
    const float* bq    = (const float*)d_in[3];
    const float* gq    = (const float*)d_in[4];
    const float* betaq = (const float*)d_in[5];
    const float* mq    = (const float*)d_in[6];
    const float* vq    = (const float*)d_in[7];
    const float* Wk    = (const float*)d_in[8];
    const float* bk    = (const float*)d_in[9];
    const float* gk    = (const float*)d_in[10];
    const float* betak = (const float*)d_in[11];
    const float* mk    = (const float*)d_in[12];
    const float* vk    = (const float*)d_in[13];
    float* out = (float*)d_out;

    fold_kernel<<<256, 256>>>(Wq, bq, gq, betaq, mq, vq, Wk, bk, gk, betak, mk, vk);
    vconv_kernel<<<(Bsz * CHW / 4 + 255) / 256, 256>>>(fea_left, fea_right);

    cudaFuncSetAttribute(proj_kernel, cudaFuncAttributeMaxDynamicSharedMemorySize, PJ_SMEM);
    proj_kernel<<<dim3(18, 2, 32), 256, PJ_SMEM>>>(fea_left, fea_right);

    cudaFuncSetAttribute(attn_kernel, cudaFuncAttributeMaxDynamicSharedMemorySize, ATT_SMEM);
    attn_kernel<<<dim3(36, 16), 128, ATT_SMEM>>>(out);
}

// round 16
// speedup vs baseline: 1.1394x; 1.1394x over previous
#include <cuda_runtime.h>
#include <cuda_fp16.h>
#include <cstdint>
#include <math.h>

#define Bsz 8
#define Cdim 256
#define HW 2304
#define CHW (Cdim*HW)          // 589824
#define BNEPS 1e-5f
#define INV_C (1.0f/256.0f)

// ---- static scratch (allocation-free), all fp16 ----
__device__ __half g_QhL[Bsz*CHW];
__device__ __half g_QhR[Bsz*CHW];
__device__ __half g_KhL[Bsz*CHW];
__device__ __half g_KhR[Bsz*CHW];
__device__ __half g_VhL[Bsz*CHW];
__device__ __half g_VhR[Bsz*CHW];

// ============================================================
// helpers
// ============================================================
__device__ __forceinline__ uint32_t smem_u32(const void* p) {
    uint32_t a;
    asm("{ .reg .u64 t; cvta.to.shared.u64 t, %1; cvt.u32.u64 %0, t; }" : "=r"(a) : "l"(p));
    return a;
}
__device__ __forceinline__ void ldsm_x4(uint32_t a, uint32_t& r0, uint32_t& r1, uint32_t& r2, uint32_t& r3) {
    asm volatile("ldmatrix.sync.aligned.m8n8.x4.shared.b16 {%0,%1,%2,%3}, [%4];"
                 : "=r"(r0), "=r"(r1), "=r"(r2), "=r"(r3) : "r"(a));
}
__device__ __forceinline__ void ldsm_x4t(uint32_t a, uint32_t& r0, uint32_t& r1, uint32_t& r2, uint32_t& r3) {
    asm volatile("ldmatrix.sync.aligned.m8n8.x4.trans.shared.b16 {%0,%1,%2,%3}, [%4];"
                 : "=r"(r0), "=r"(r1), "=r"(r2), "=r"(r3) : "r"(a));
}
__device__ __forceinline__ void ldsm_x2t(uint32_t a, uint32_t& r0, uint32_t& r1) {
    asm volatile("ldmatrix.sync.aligned.m8n8.x2.trans.shared.b16 {%0,%1}, [%2];"
                 : "=r"(r0), "=r"(r1) : "r"(a));
}
__device__ __forceinline__ void mma_f16(float* c, const uint32_t* a, const uint32_t* b) {
    asm volatile("mma.sync.aligned.m16n8k16.row.col.f32.f16.f16.f32 "
                 "{%0,%1,%2,%3}, {%4,%5,%6,%7}, {%8,%9}, {%0,%1,%2,%3};"
                 : "+f"(c[0]), "+f"(c[1]), "+f"(c[2]), "+f"(c[3])
                 : "r"(a[0]), "r"(a[1]), "r"(a[2]), "r"(a[3]), "r"(b[0]), "r"(b[1]));
}
__device__ __forceinline__ uint32_t pack2h(float a, float b) {
    __half2 t = __floats2half2_rn(a, b);
    return *(uint32_t*)&t;
}
#define CP_ASYNC16(dst, src) \
    asm volatile("cp.async.cg.shared.global [%0], [%1], 16;" :: "r"(dst), "l"(src) : "memory")
#define CP_COMMIT() asm volatile("cp.async.commit_group;" ::: "memory")
#define CP_WAIT0()  asm volatile("cp.async.wait_group 0;" ::: "memory")
#define BAR_PAIR(id) asm volatile("bar.sync %0, 64;" :: "r"(id) : "memory")

// ============================================================
// V convert: fea fp32 -> fp16 scratch (both sides)
// ============================================================
__global__ void vconv_kernel(const float* __restrict__ fleft, const float* __restrict__ fright)
{
    int i = blockIdx.x * blockDim.x + threadIdx.x;      // float4 index
    const int n4 = (Bsz * CHW) / 4;
    if (i >= n4) return;
    float4 a = ((const float4*)fleft)[i];
    float4 b = ((const float4*)fright)[i];
    ((uint2*)g_VhL)[i] = make_uint2(pack2h(a.x, a.y), pack2h(a.z, a.w));
    ((uint2*)g_VhR)[i] = make_uint2(pack2h(b.x, b.y), pack2h(b.z, b.w));
}

// ============================================================
// Projection GEMM via fp16 mma, BN fold inlined:
// dst[o][n] = sum_c (W[o][c]*s[o]) X[c][n] + bias[o]
// s = g*rsqrt(v+eps); bias = (b-m)*s + beta   (computed per CTA into smem)
// grid (18 n-tiles, 2 o-tiles, 32 = p*8+b), 256 threads (8 warps). fp16 out.
// ============================================================
#define PJ_WOFF 0
#define PJ_XOFF 67584
#define PJ_SOFF (67584 + 32*272)
#define PJ_BOFF (PJ_SOFF + 1024)
#define PJ_SMEM (PJ_BOFF + 1024)

__global__ void __launch_bounds__(256, 2)
proj_kernel(const float* __restrict__ fleft, const float* __restrict__ fright,
            const float* __restrict__ Wq, const float* __restrict__ bq,
            const float* __restrict__ gq, const float* __restrict__ betaq,
            const float* __restrict__ mq, const float* __restrict__ vq,
            const float* __restrict__ Wk, const float* __restrict__ bk,
            const float* __restrict__ gk, const float* __restrict__ betak,
            const float* __restrict__ mk, const float* __restrict__ vk)
{
    extern __shared__ char sm[];
    uint32_t sb = smem_u32(sm);
    int tid = threadIdx.x;
    int t = tid & 31, w = tid >> 5;

    int z = blockIdx.z;
    int p = z >> 3, b = z & 7;
    const float* X   = ((p & 1) ? fright : fleft) + b * CHW;
    const float* Wr  = (p < 2) ? Wq : Wk;
    const float* br  = (p < 2) ? bq : bk;
    const float* gr  = (p < 2) ? gq : gk;
    const float* ber = (p < 2) ? betaq : betak;
    const float* mr  = (p < 2) ? mq : mk;
    const float* vr  = (p < 2) ? vq : vk;
    __half* dst =
        ((p == 0) ? g_QhL : (p == 1) ? g_QhR : (p == 2) ? g_KhL : g_KhR) + b * CHW;

    float* sS = (float*)(sm + PJ_SOFF);
    float* bS = (float*)(sm + PJ_BOFF);
    {
        int o = tid;    // 256 threads = 256 channels
        float s = gr[o] * rsqrtf(vr[o] + BNEPS);
        sS[o] = s;
        bS[o] = (br[o] - mr[o]) * s + ber[o];
    }
    __syncthreads();

    int n0 = blockIdx.x * 128, o0 = blockIdx.y * 128;

    // load W tile [128 o][256 c] fp32 -> fp16 with BN scale folded
    #pragma unroll
    for (int it = 0; it < 32; it++) {
        int idx = tid + it * 256;
        int r = idx >> 6, c4 = idx & 63;
        float sc = sS[o0 + r];
        float4 v = *(const float4*)(Wr + (o0 + r) * 256 + c4 * 4);
        *(uint2*)(sm + PJ_WOFF + r * 528 + c4 * 8) =
            make_uint2(pack2h(v.x * sc, v.y * sc), pack2h(v.z * sc, v.w * sc));
    }

    float oacc[16][4];
    #pragma unroll
    for (int i = 0; i < 16; i++)
        #pragma unroll
        for (int j = 0; j < 4; j++) oacc[i][j] = 0.0f;

    uint32_t aW = sb + PJ_WOFF + (w * 16 + (t & 7) + ((t >> 3) & 1) * 8) * 528 + (t >> 4) * 16;
    uint32_t bX = sb + PJ_XOFF + (t & 15) * 272;

    #pragma unroll 1
    for (int ch = 0; ch < 8; ch++) {
        __syncthreads();
        #pragma unroll
        for (int it = 0; it < 4; it++) {
            int idx = tid + it * 256;
            int rc = idx >> 5, n4 = idx & 31;
            float4 v = *(const float4*)(X + (ch * 32 + rc) * HW + n0 + n4 * 4);
            *(uint2*)(sm + PJ_XOFF + rc * 272 + n4 * 8) = make_uint2(pack2h(v.x, v.y), pack2h(v.z, v.w));
        }
        __syncthreads();

        #pragma unroll
        for (int ksl = 0; ksl < 2; ksl++) {
            uint32_t a[4];
            ldsm_x4(aW + ch * 64 + ksl * 32, a[0], a[1], a[2], a[3]);
            #pragma unroll
            for (int nt = 0; nt < 16; nt++) {
                uint32_t bb[2];
                ldsm_x2t(bX + ksl * 16 * 272 + nt * 16, bb[0], bb[1]);
                mma_f16(oacc[nt], a, bb);
            }
        }
    }

    int r0 = o0 + w * 16 + (t >> 2);
    float b0 = bS[r0], b1 = bS[r0 + 8];
    #pragma unroll
    for (int nt = 0; nt < 16; nt++) {
        int col = n0 + nt * 8 + (t & 3) * 2;
        *(uint32_t*)(dst + r0 * HW + col)       = pack2h(oacc[nt][0] + b0, oacc[nt][1] + b0);
        *(uint32_t*)(dst + (r0 + 8) * HW + col) = pack2h(oacc[nt][2] + b1, oacc[nt][3] + b1);
    }
}

// ============================================================
// Flash attention (R14 structure), K/V fragments via ldsm_x4 (2 nt per issue).
// 128 q-rows/CTA, 36 key tiles of 64. 256 threads = 8 warps:
// g = w>>1 owns 32 rows (2 A-frags), h = w&1 (32-key half for S, 128-d half for PV).
// smem: Qs[128][528B] | Ks[2][64][528B] | Vs[2][64][528B] | Ps fp16[128][144B] | li[128]
// ============================================================
#define AQOFF 0
#define AKOFF 67584
#define AVOFF 135168
#define APOFF 202752
#define ALOFF 221184
#define ATT_SMEM 221696
#define KVT 33792            // 64*528

__global__ void __launch_bounds__(256, 1)
attn_kernel(float* __restrict__ out)
{
    extern __shared__ char sm[];
    uint32_t sb = smem_u32(sm);
    int tid = threadIdx.x;
    int t = tid & 31, w = tid >> 5;
    int g = w >> 1, h = w & 1;

    int u = blockIdx.y;
    int att = u >> 3, b = u & 7;
    const __half* Q = (att == 0 ? g_QhL : g_QhR) + b * CHW;
    const __half* K = (att == 0 ? g_KhR : g_KhL) + b * CHW;
    const __half* V = (att == 0 ? g_VhR : g_VhL) + b * CHW;
    float* O = out + att * (Bsz * CHW) + b * CHW;
    int q0 = blockIdx.x * 128;

    if (tid < 128) *(float*)(sm + ALOFF + tid * 4) = 0.0f;

    // Q tile via cp.async: 128 rows x 32 chunks of 16B
    #pragma unroll
    for (int it = 0; it < 16; it++) {
        int idx = tid + it * 256;
        int r = idx >> 5, c16 = idx & 31;
        CP_ASYNC16(sb + AQOFF + r * 528 + c16 * 16, (const char*)(Q + (q0 + r) * 256) + c16 * 16);
    }
    // K/V tile 0 into buffer 0 (64 rows x 32 chunks each)
    #pragma unroll
    for (int it = 0; it < 8; it++) {
        int idx = tid + it * 256;
        int r = idx >> 5, c16 = idx & 31;
        CP_ASYNC16(sb + AKOFF + r * 528 + c16 * 16, (const char*)(K + r * 256) + c16 * 16);
        CP_ASYNC16(sb + AVOFF + r * 528 + c16 * 16, (const char*)(V + r * 256) + c16 * 16);
    }
    CP_COMMIT();

    int m0 = g * 32;            // 32-row group
    int n0 = h * 32;            // 32-key half (S phase)
    int nd0 = h * 128;          // 128-d half (PV phase)

    uint32_t aQ0 = sb + AQOFF + (m0 + (t & 7) + ((t >> 3) & 1) * 8) * 528 + (t >> 4) * 16;
    uint32_t aQ1 = aQ0 + 16 * 528;
    int r0 = m0 + (t >> 2);
    uint32_t aP0 = sb + APOFF + (m0 + (t & 7) + ((t >> 3) & 1) * 8) * 144 + (t >> 4) * 16;
    uint32_t aP1 = aP0 + 16 * 144;

    float oacc[2][16][4];
    #pragma unroll
    for (int f = 0; f < 2; f++)
        #pragma unroll
        for (int i = 0; i < 16; i++)
            #pragma unroll
            for (int j = 0; j < 4; j++) oacc[f][i][j] = 0.0f;
    float li00 = 0.0f, li01 = 0.0f, li10 = 0.0f, li11 = 0.0f;

    #pragma unroll 1
    for (int kt = 0; kt < 36; kt++) {
        int buf = kt & 1;
        uint32_t kbase = sb + AKOFF + buf * KVT;
        uint32_t vbase = sb + AVOFF + buf * KVT;

        CP_WAIT0();
        __syncthreads();      // tile kt resident; prev iter's K/V consumers done

        // prefetch tile kt+1 into other buffer
        if (kt < 35) {
            int k0n = (kt + 1) * 64;
            uint32_t kd = sb + AKOFF + (buf ^ 1) * KVT;
            uint32_t vd = sb + AVOFF + (buf ^ 1) * KVT;
            #pragma unroll
            for (int it = 0; it < 8; it++) {
                int idx = tid + it * 256;
                int r = idx >> 5, c16 = idx & 31;
                CP_ASYNC16(kd + r * 528 + c16 * 16, (const char*)(K + (k0n + r) * 256) + c16 * 16);
                CP_ASYNC16(vd + r * 528 + c16 * 16, (const char*)(V + (k0n + r) * 256) + c16 * 16);
            }
            CP_COMMIT();
        }

        // ---- S = Q K^T (fp16): warp computes S[32 x 32] via 2 A-frags ----
        // K via ldsm_x4: matrices = (nt-pair, k-half) combos; lanes 16-31 -> rows +8.
        uint32_t bK4 = kbase + (n0 + (t & 7) + ((t >> 4) << 3)) * 528 + ((t >> 3) & 1) * 16;
        float sacc[2][4][4];
        #pragma unroll
        for (int f = 0; f < 2; f++)
            #pragma unroll
            for (int i = 0; i < 4; i++)
                #pragma unroll
                for (int j = 0; j < 4; j++) sacc[f][i][j] = 0.0f;
        #pragma unroll
        for (int ks = 0; ks < 16; ks++) {
            uint32_t a0[4], a1[4];
            ldsm_x4(aQ0 + ks * 32, a0[0], a0[1], a0[2], a0[3]);
            ldsm_x4(aQ1 + ks * 32, a1[0], a1[1], a1[2], a1[3]);
            #pragma unroll
            for (int nt2 = 0; nt2 < 2; nt2++) {
                uint32_t kb[4];
                ldsm_x4(bK4 + nt2 * 16 * 528 + ks * 32, kb[0], kb[1], kb[2], kb[3]);
                mma_f16(sacc[0][nt2 * 2],     a0, kb);
                mma_f16(sacc[1][nt2 * 2],     a1, kb);
                mma_f16(sacc[0][nt2 * 2 + 1], a0, kb + 2);
                mma_f16(sacc[1][nt2 * 2 + 1], a1, kb + 2);
            }
        }

        // ---- softmax (no max subtraction) + store P (fp16) ----
        #pragma unroll
        for (int f = 0; f < 2; f++) {
            int rf = r0 + f * 16;
            #pragma unroll
            for (int nt = 0; nt < 4; nt++) {
                float p0 = __expf(sacc[f][nt][0] * INV_C);
                float p1 = __expf(sacc[f][nt][1] * INV_C);
                float p2 = __expf(sacc[f][nt][2] * INV_C);
                float p3 = __expf(sacc[f][nt][3] * INV_C);
                if (f == 0) { li00 += p0 + p1; li01 += p2 + p3; }
                else        { li10 += p0 + p1; li11 += p2 + p3; }
                int col = n0 + nt * 8 + (t & 3) * 2;
                *(uint32_t*)(sm + APOFF + rf * 144 + col * 2)       = pack2h(p0, p1);
                *(uint32_t*)(sm + APOFF + (rf + 8) * 144 + col * 2) = pack2h(p2, p3);
            }
        }
        BAR_PAIR(g + 1);   // P rows [m0, m0+32) complete (pair-local hazard only)

        // ---- O += P @ V (fp16): V via ldsm_x4t (2 nt per issue) ----
        uint32_t bV4 = vbase + (t & 15) * 528 + ((t >> 4) << 4) + nd0 * 2;
        #pragma unroll
        for (int ks = 0; ks < 4; ks++) {
            uint32_t a0[4], a1[4];
            ldsm_x4(aP0 + ks * 32, a0[0], a0[1], a0[2], a0[3]);
            ldsm_x4(aP1 + ks * 32, a1[0], a1[1], a1[2], a1[3]);
            #pragma unroll
            for (int nt2 = 0; nt2 < 8; nt2++) {
                uint32_t vb[4];
                ldsm_x4t(bV4 + ks * 16 * 528 + nt2 * 32, vb[0], vb[1], vb[2], vb[3]);
                mma_f16(oacc[0][nt2 * 2],     a0, vb);
                mma_f16(oacc[1][nt2 * 2],     a1, vb);
                mma_f16(oacc[0][nt2 * 2 + 1], a0, vb + 2);
                mma_f16(oacc[1][nt2 * 2 + 1], a1, vb + 2);
            }
        }
    }

    // ---- li reduction (4 rows per thread) ----
    li00 += __shfl_xor_sync(0xFFFFFFFFu, li00, 1);
    li00 += __shfl_xor_sync(0xFFFFFFFFu, li00, 2);
    li01 += __shfl_xor_sync(0xFFFFFFFFu, li01, 1);
    li01 += __shfl_xor_sync(0xFFFFFFFFu, li01, 2);
    li10 += __shfl_xor_sync(0xFFFFFFFFu, li10, 1);
    li10 += __shfl_xor_sync(0xFFFFFFFFu, li10, 2);
    li11 += __shfl_xor_sync(0xFFFFFFFFu, li11, 1);
    li11 += __shfl_xor_sync(0xFFFFFFFFu, li11, 2);
    if ((t & 3) == 0) {
        atomicAdd((float*)(sm + ALOFF + r0 * 4), li00);
        atomicAdd((float*)(sm + ALOFF + (r0 + 8) * 4), li01);
        atomicAdd((float*)(sm + ALOFF + (r0 + 16) * 4), li10);
        atomicAdd((float*)(sm + ALOFF + (r0 + 24) * 4), li11);
    }
    __syncthreads();

    // ---- epilogue: O[r][d]/li -> out[d*HW + q0 + r] ----
    float rl00 = 1.0f / *(float*)(sm + ALOFF + r0 * 4);
    float rl01 = 1.0f / *(float*)(sm + ALOFF + (r0 + 8) * 4);
    float rl10 = 1.0f / *(float*)(sm + ALOFF + (r0 + 16) * 4);
    float rl11 = 1.0f / *(float*)(sm + ALOFF + (r0 + 24) * 4);
    #pragma unroll
    for (int nt = 0; nt < 16; nt++) {
        int col = nd0 + nt * 8 + (t & 3) * 2;
        O[col * HW + q0 + r0]            = oacc[0][nt][0] * rl00;
        O[(col + 1) * HW + q0 + r0]      = oacc[0][nt][1] * rl00;
        O[col * HW + q0 + r0 + 8]        = oacc[0][nt][2] * rl01;
        O[(col + 1) * HW + q0 + r0 + 8]  = oacc[0][nt][3] * rl01;
        O[col * HW + q0 + r0 + 16]       = oacc[1][nt][0] * rl10;
        O[(col + 1) * HW + q0 + r0 + 16] = oacc[1][nt][1] * rl10;
        O[col * HW + q0 + r0 + 24]       = oacc[1][nt][2] * rl11;
        O[(col + 1) * HW + q0 + r0 + 24] = oacc[1][nt][3] * rl11;
    }
}

extern "C" void kernel_launch(void* const* d_in, const int* in_sizes, int n_in,
                              void* d_out, int out_size)
{
    const float* fea_left  = (const float*)d_in[0];
    const float* fea_right = (const float*)d_in[1];
    const float* Wq    = (const float*)d_in[2];
    const float* bq    = (const float*)d_in[3];
    const float* gq    = (const float*)d_in[4];
    const float* betaq = (const float*)d_in[5];
    const float* mq    = (const float*)d_in[6];
    const float* vq    = (const float*)d_in[7];
    const float* Wk    = (const float*)d_in[8];
    const float* bk    = (const float*)d_in[9];
    const float* gk    = (const float*)d_in[10];
    const float* betak = (const float*)d_in[11];
    const float* mk    = (const float*)d_in[12];
    const float* vk    = (const float*)d_in[13];
    float* out = (float*)d_out;

    vconv_kernel<<<(Bsz * CHW / 4 + 255) / 256, 256>>>(fea_left, fea_right);

    cudaFuncSetAttribute(proj_kernel, cudaFuncAttributeMaxDynamicSharedMemorySize, PJ_SMEM);
    proj_kernel<<<dim3(18, 2, 32), 256, PJ_SMEM>>>(fea_left, fea_right,
        Wq, bq, gq, betaq, mq, vq, Wk, bk, gk, betak, mk, vk);

    cudaFuncSetAttribute(attn_kernel, cudaFuncAttributeMaxDynamicSharedMemorySize, ATT_SMEM);
    attn_kernel<<<dim3(18, 16), 256, ATT_SMEM>>>(out);
}

// round 17
// speedup vs baseline: 1.1531x; 1.0120x over previous
#include <cuda_runtime.h>
#include <cuda_fp16.h>
#include <cstdint>
#include <math.h>

#define Bsz 8
#define Cdim 256
#define HW 2304
#define CHW (Cdim*HW)          // 589824
#define BNEPS 1e-5f
#define ALPHA (1.4426950408889634f/256.0f)   // log2(e)/256, folded into Q

// ---- static scratch (allocation-free), all fp16 ----
__device__ __half g_QhL[Bsz*CHW];
__device__ __half g_QhR[Bsz*CHW];
__device__ __half g_KhL[Bsz*CHW];
__device__ __half g_KhR[Bsz*CHW];
__device__ __half g_VhL[Bsz*CHW];
__device__ __half g_VhR[Bsz*CHW];

// ============================================================
// helpers
// ============================================================
__device__ __forceinline__ uint32_t smem_u32(const void* p) {
    uint32_t a;
    asm("{ .reg .u64 t; cvta.to.shared.u64 t, %1; cvt.u32.u64 %0, t; }" : "=r"(a) : "l"(p));
    return a;
}
__device__ __forceinline__ void ldsm_x4(uint32_t a, uint32_t& r0, uint32_t& r1, uint32_t& r2, uint32_t& r3) {
    asm volatile("ldmatrix.sync.aligned.m8n8.x4.shared.b16 {%0,%1,%2,%3}, [%4];"
                 : "=r"(r0), "=r"(r1), "=r"(r2), "=r"(r3) : "r"(a));
}
__device__ __forceinline__ void ldsm_x4t(uint32_t a, uint32_t& r0, uint32_t& r1, uint32_t& r2, uint32_t& r3) {
    asm volatile("ldmatrix.sync.aligned.m8n8.x4.trans.shared.b16 {%0,%1,%2,%3}, [%4];"
                 : "=r"(r0), "=r"(r1), "=r"(r2), "=r"(r3) : "r"(a));
}
__device__ __forceinline__ void mma_f16(float* c, const uint32_t* a, const uint32_t* b) {
    asm volatile("mma.sync.aligned.m16n8k16.row.col.f32.f16.f16.f32 "
                 "{%0,%1,%2,%3}, {%4,%5,%6,%7}, {%8,%9}, {%0,%1,%2,%3};"
                 : "+f"(c[0]), "+f"(c[1]), "+f"(c[2]), "+f"(c[3])
                 : "r"(a[0]), "r"(a[1]), "r"(a[2]), "r"(a[3]), "r"(b[0]), "r"(b[1]));
}
__device__ __forceinline__ uint32_t pack2h(float a, float b) {
    __half2 t = __floats2half2_rn(a, b);
    return *(uint32_t*)&t;
}
// cvt two fp32 -> f16x2 (lo, hi)
__device__ __forceinline__ uint32_t cvt2h(float lo, float hi) {
    uint32_t d;
    asm("cvt.rn.f16x2.f32 %0, %1, %2;" : "=r"(d) : "f"(hi), "f"(lo));
    return d;
}
__device__ __forceinline__ uint32_t ex2h2(uint32_t x) {
    uint32_t d;
    asm("ex2.approx.f16x2 %0, %1;" : "=r"(d) : "r"(x));
    return d;
}
#define CP_ASYNC16(dst, src) \
    asm volatile("cp.async.cg.shared.global [%0], [%1], 16;" :: "r"(dst), "l"(src) : "memory")
#define CP_COMMIT() asm volatile("cp.async.commit_group;" ::: "memory")
#define CP_WAIT0()  asm volatile("cp.async.wait_group 0;" ::: "memory")
#define BAR_PAIR(id) asm volatile("bar.sync %0, 64;" :: "r"(id) : "memory")

// ============================================================
// V convert: fea fp32 -> fp16 scratch (both sides)
// ============================================================
__global__ void vconv_kernel(const float* __restrict__ fleft, const float* __restrict__ fright)
{
    int i = blockIdx.x * blockDim.x + threadIdx.x;      // float4 index
    const int n4 = (Bsz * CHW) / 4;
    if (i >= n4) return;
    float4 a = ((const float4*)fleft)[i];
    float4 b = ((const float4*)fright)[i];
    ((uint2*)g_VhL)[i] = make_uint2(pack2h(a.x, a.y), pack2h(a.z, a.w));
    ((uint2*)g_VhR)[i] = make_uint2(pack2h(b.x, b.y), pack2h(b.z, b.w));
}

// ============================================================
// Projection GEMM via fp16 mma, BN fold inlined.
// Q branch (p<2) additionally folds ALPHA = log2e/256 into scale+bias so the
// attention S accumulator lands directly in the log2 domain.
// grid (18 n-tiles, 2 o-tiles, 32 = p*8+b), 256 threads (8 warps). fp16 out.
// ============================================================
#define PJ_WOFF 0
#define PJ_XOFF 67584
#define PJ_SOFF (67584 + 32*272)
#define PJ_BOFF (PJ_SOFF + 1024)
#define PJ_SMEM (PJ_BOFF + 1024)

__global__ void __launch_bounds__(256, 2)
proj_kernel(const float* __restrict__ fleft, const float* __restrict__ fright,
            const float* __restrict__ Wq, const float* __restrict__ bq,
            const float* __restrict__ gq, const float* __restrict__ betaq,
            const float* __restrict__ mq, const float* __restrict__ vq,
            const float* __restrict__ Wk, const float* __restrict__ bk,
            const float* __restrict__ gk, const float* __restrict__ betak,
            const float* __restrict__ mk, const float* __restrict__ vk)
{
    extern __shared__ char sm[];
    uint32_t sb = smem_u32(sm);
    int tid = threadIdx.x;
    int t = tid & 31, w = tid >> 5;

    int z = blockIdx.z;
    int p = z >> 3, b = z & 7;
    const float* X   = ((p & 1) ? fright : fleft) + b * CHW;
    const float* Wr  = (p < 2) ? Wq : Wk;
    const float* br  = (p < 2) ? bq : bk;
    const float* gr  = (p < 2) ? gq : gk;
    const float* ber = (p < 2) ? betaq : betak;
    const float* mr  = (p < 2) ? mq : mk;
    const float* vr  = (p < 2) ? vq : vk;
    __half* dst =
        ((p == 0) ? g_QhL : (p == 1) ? g_QhR : (p == 2) ? g_KhL : g_KhR) + b * CHW;

    float* sS = (float*)(sm + PJ_SOFF);
    float* bS = (float*)(sm + PJ_BOFF);
    {
        int o = tid;    // 256 threads = 256 channels
        float al = (p < 2) ? ALPHA : 1.0f;
        float s = gr[o] * rsqrtf(vr[o] + BNEPS) * al;
        sS[o] = s;
        bS[o] = (br[o] - mr[o]) * s + ber[o] * al;
    }
    __syncthreads();

    int n0 = blockIdx.x * 128, o0 = blockIdx.y * 128;

    // load W tile [128 o][256 c] fp32 -> fp16 with BN scale (and ALPHA) folded
    #pragma unroll
    for (int it = 0; it < 32; it++) {
        int idx = tid + it * 256;
        int r = idx >> 6, c4 = idx & 63;
        float sc = sS[o0 + r];
        float4 v = *(const float4*)(Wr + (o0 + r) * 256 + c4 * 4);
        *(uint2*)(sm + PJ_WOFF + r * 528 + c4 * 8) =
            make_uint2(pack2h(v.x * sc, v.y * sc), pack2h(v.z * sc, v.w * sc));
    }

    float oacc[16][4];
    #pragma unroll
    for (int i = 0; i < 16; i++)
        #pragma unroll
        for (int j = 0; j < 4; j++) oacc[i][j] = 0.0f;

    uint32_t aW = sb + PJ_WOFF + (w * 16 + (t & 7) + ((t >> 3) & 1) * 8) * 528 + (t >> 4) * 16;
    uint32_t bX4 = sb + PJ_XOFF + (t & 15) * 272 + ((t >> 4) << 4);

    #pragma unroll 1
    for (int ch = 0; ch < 8; ch++) {
        __syncthreads();
        #pragma unroll
        for (int it = 0; it < 4; it++) {
            int idx = tid + it * 256;
            int rc = idx >> 5, n4 = idx & 31;
            float4 v = *(const float4*)(X + (ch * 32 + rc) * HW + n0 + n4 * 4);
            *(uint2*)(sm + PJ_XOFF + rc * 272 + n4 * 8) = make_uint2(pack2h(v.x, v.y), pack2h(v.z, v.w));
        }
        __syncthreads();

        #pragma unroll
        for (int ksl = 0; ksl < 2; ksl++) {
            uint32_t a[4];
            ldsm_x4(aW + ch * 64 + ksl * 32, a[0], a[1], a[2], a[3]);
            #pragma unroll
            for (int nt2 = 0; nt2 < 8; nt2++) {
                uint32_t xb[4];
                ldsm_x4t(bX4 + ksl * 16 * 272 + nt2 * 32, xb[0], xb[1], xb[2], xb[3]);
                mma_f16(oacc[nt2 * 2],     a, xb);
                mma_f16(oacc[nt2 * 2 + 1], a, xb + 2);
            }
        }
    }

    int r0 = o0 + w * 16 + (t >> 2);
    float b0 = bS[r0], b1 = bS[r0 + 8];
    #pragma unroll
    for (int nt = 0; nt < 16; nt++) {
        int col = n0 + nt * 8 + (t & 3) * 2;
        *(uint32_t*)(dst + r0 * HW + col)       = pack2h(oacc[nt][0] + b0, oacc[nt][1] + b0);
        *(uint32_t*)(dst + (r0 + 8) * HW + col) = pack2h(oacc[nt][2] + b1, oacc[nt][3] + b1);
    }
}

// ============================================================
// Flash attention (R16 structure). Softmax via ex2.approx.f16x2:
// sacc is already log2(P) (ALPHA folded into Q), so P = ex2(sacc) with one
// cvt + one f16x2-MUFU per value pair; li summed from the stored f16 values.
// 128 q-rows/CTA, 36 key tiles of 64. 256 threads = 8 warps:
// g = w>>1 owns 32 rows (2 A-frags), h = w&1 (32-key half S, 128-d half PV).
// smem: Qs[128][528B] | Ks[2][64][528B] | Vs[2][64][528B] | Ps fp16[128][144B] | li[128]
// ============================================================
#define AQOFF 0
#define AKOFF 67584
#define AVOFF 135168
#define APOFF 202752
#define ALOFF 221184
#define ATT_SMEM 221696
#define KVT 33792            // 64*528

__global__ void __launch_bounds__(256, 1)
attn_kernel(float* __restrict__ out)
{
    extern __shared__ char sm[];
    uint32_t sb = smem_u32(sm);
    int tid = threadIdx.x;
    int t = tid & 31, w = tid >> 5;
    int g = w >> 1, h = w & 1;

    int u = blockIdx.y;
    int att = u >> 3, b = u & 7;
    const __half* Q = (att == 0 ? g_QhL : g_QhR) + b * CHW;
    const __half* K = (att == 0 ? g_KhR : g_KhL) + b * CHW;
    const __half* V = (att == 0 ? g_VhR : g_VhL) + b * CHW;
    float* O = out + att * (Bsz * CHW) + b * CHW;
    int q0 = blockIdx.x * 128;

    if (tid < 128) *(float*)(sm + ALOFF + tid * 4) = 0.0f;

    // Q tile via cp.async: 128 rows x 32 chunks of 16B
    #pragma unroll
    for (int it = 0; it < 16; it++) {
        int idx = tid + it * 256;
        int r = idx >> 5, c16 = idx & 31;
        CP_ASYNC16(sb + AQOFF + r * 528 + c16 * 16, (const char*)(Q + (q0 + r) * 256) + c16 * 16);
    }
    // K/V tile 0 into buffer 0 (64 rows x 32 chunks each)
    #pragma unroll
    for (int it = 0; it < 8; it++) {
        int idx = tid + it * 256;
        int r = idx >> 5, c16 = idx & 31;
        CP_ASYNC16(sb + AKOFF + r * 528 + c16 * 16, (const char*)(K + r * 256) + c16 * 16);
        CP_ASYNC16(sb + AVOFF + r * 528 + c16 * 16, (const char*)(V + r * 256) + c16 * 16);
    }
    CP_COMMIT();

    int m0 = g * 32;            // 32-row group
    int n0 = h * 32;            // 32-key half (S phase)
    int nd0 = h * 128;          // 128-d half (PV phase)

    uint32_t aQ0 = sb + AQOFF + (m0 + (t & 7) + ((t >> 3) & 1) * 8) * 528 + (t >> 4) * 16;
    uint32_t aQ1 = aQ0 + 16 * 528;
    int r0 = m0 + (t >> 2);
    uint32_t aP0 = sb + APOFF + (m0 + (t & 7) + ((t >> 3) & 1) * 8) * 144 + (t >> 4) * 16;
    uint32_t aP1 = aP0 + 16 * 144;

    float oacc[2][16][4];
    #pragma unroll
    for (int f = 0; f < 2; f++)
        #pragma unroll
        for (int i = 0; i < 16; i++)
            #pragma unroll
            for (int j = 0; j < 4; j++) oacc[f][i][j] = 0.0f;
    float li00 = 0.0f, li01 = 0.0f, li10 = 0.0f, li11 = 0.0f;

    #pragma unroll 1
    for (int kt = 0; kt < 36; kt++) {
        int buf = kt & 1;
        uint32_t kbase = sb + AKOFF + buf * KVT;
        uint32_t vbase = sb + AVOFF + buf * KVT;

        CP_WAIT0();
        __syncthreads();      // tile kt resident; prev iter's K/V consumers done

        // prefetch tile kt+1 into other buffer
        if (kt < 35) {
            int k0n = (kt + 1) * 64;
            uint32_t kd = sb + AKOFF + (buf ^ 1) * KVT;
            uint32_t vd = sb + AVOFF + (buf ^ 1) * KVT;
            #pragma unroll
            for (int it = 0; it < 8; it++) {
                int idx = tid + it * 256;
                int r = idx >> 5, c16 = idx & 31;
                CP_ASYNC16(kd + r * 528 + c16 * 16, (const char*)(K + (k0n + r) * 256) + c16 * 16);
                CP_ASYNC16(vd + r * 528 + c16 * 16, (const char*)(V + (k0n + r) * 256) + c16 * 16);
            }
            CP_COMMIT();
        }

        // ---- S = Q K^T (fp16): warp computes S[32 x 32] via 2 A-frags ----
        uint32_t bK4 = kbase + (n0 + (t & 7) + ((t >> 4) << 3)) * 528 + ((t >> 3) & 1) * 16;
        float sacc[2][4][4];
        #pragma unroll
        for (int f = 0; f < 2; f++)
            #pragma unroll
            for (int i = 0; i < 4; i++)
                #pragma unroll
                for (int j = 0; j < 4; j++) sacc[f][i][j] = 0.0f;
        #pragma unroll
        for (int ks = 0; ks < 16; ks++) {
            uint32_t a0[4], a1[4];
            ldsm_x4(aQ0 + ks * 32, a0[0], a0[1], a0[2], a0[3]);
            ldsm_x4(aQ1 + ks * 32, a1[0], a1[1], a1[2], a1[3]);
            #pragma unroll
            for (int nt2 = 0; nt2 < 2; nt2++) {
                uint32_t kb[4];
                ldsm_x4(bK4 + nt2 * 16 * 528 + ks * 32, kb[0], kb[1], kb[2], kb[3]);
                mma_f16(sacc[0][nt2 * 2],     a0, kb);
                mma_f16(sacc[1][nt2 * 2],     a1, kb);
                mma_f16(sacc[0][nt2 * 2 + 1], a0, kb + 2);
                mma_f16(sacc[1][nt2 * 2 + 1], a1, kb + 2);
            }
        }

        // ---- softmax: P = ex2(sacc) in f16x2; li from the stored f16 values ----
        #pragma unroll
        for (int f = 0; f < 2; f++) {
            int rf = r0 + f * 16;
            #pragma unroll
            for (int nt = 0; nt < 4; nt++) {
                uint32_t e01 = ex2h2(cvt2h(sacc[f][nt][0], sacc[f][nt][1]));
                uint32_t e23 = ex2h2(cvt2h(sacc[f][nt][2], sacc[f][nt][3]));
                float2 f01 = __half22float2(*(__half2*)&e01);
                float2 f23 = __half22float2(*(__half2*)&e23);
                if (f == 0) { li00 += f01.x + f01.y; li01 += f23.x + f23.y; }
                else        { li10 += f01.x + f01.y; li11 += f23.x + f23.y; }
                int col = n0 + nt * 8 + (t & 3) * 2;
                *(uint32_t*)(sm + APOFF + rf * 144 + col * 2)       = e01;
                *(uint32_t*)(sm + APOFF + (rf + 8) * 144 + col * 2) = e23;
            }
        }
        BAR_PAIR(g + 1);   // P rows [m0, m0+32) complete (pair-local hazard only)

        // ---- O += P @ V (fp16): V via ldsm_x4t (2 nt per issue) ----
        uint32_t bV4 = vbase + (t & 15) * 528 + ((t >> 4) << 4) + nd0 * 2;
        #pragma unroll
        for (int ks = 0; ks < 4; ks++) {
            uint32_t a0[4], a1[4];
            ldsm_x4(aP0 + ks * 32, a0[0], a0[1], a0[2], a0[3]);
            ldsm_x4(aP1 + ks * 32, a1[0], a1[1], a1[2], a1[3]);
            #pragma unroll
            for (int nt2 = 0; nt2 < 8; nt2++) {
                uint32_t vb[4];
                ldsm_x4t(bV4 + ks * 16 * 528 + nt2 * 32, vb[0], vb[1], vb[2], vb[3]);
                mma_f16(oacc[0][nt2 * 2],     a0, vb);
                mma_f16(oacc[1][nt2 * 2],     a1, vb);
                mma_f16(oacc[0][nt2 * 2 + 1], a0, vb + 2);
                mma_f16(oacc[1][nt2 * 2 + 1], a1, vb + 2);
            }
        }
    }

    // ---- li reduction (4 rows per thread) ----
    li00 += __shfl_xor_sync(0xFFFFFFFFu, li00, 1);
    li00 += __shfl_xor_sync(0xFFFFFFFFu, li00, 2);
    li01 += __shfl_xor_sync(0xFFFFFFFFu, li01, 1);
    li01 += __shfl_xor_sync(0xFFFFFFFFu, li01, 2);
    li10 += __shfl_xor_sync(0xFFFFFFFFu, li10, 1);
    li10 += __shfl_xor_sync(0xFFFFFFFFu, li10, 2);
    li11 += __shfl_xor_sync(0xFFFFFFFFu, li11, 1);
    li11 += __shfl_xor_sync(0xFFFFFFFFu, li11, 2);
    if ((t & 3) == 0) {
        atomicAdd((float*)(sm + ALOFF + r0 * 4), li00);
        atomicAdd((float*)(sm + ALOFF + (r0 + 8) * 4), li01);
        atomicAdd((float*)(sm + ALOFF + (r0 + 16) * 4), li10);
        atomicAdd((float*)(sm + ALOFF + (r0 + 24) * 4), li11);
    }
    __syncthreads();

    // ---- epilogue: O[r][d]/li -> out[d*HW + q0 + r] ----
    float rl00 = 1.0f / *(float*)(sm + ALOFF + r0 * 4);
    float rl01 = 1.0f / *(float*)(sm + ALOFF + (r0 + 8) * 4);
    float rl10 = 1.0f / *(float*)(sm + ALOFF + (r0 + 16) * 4);
    float rl11 = 1.0f / *(float*)(sm + ALOFF + (r0 + 24) * 4);
    #pragma unroll
    for (int nt = 0; nt < 16; nt++) {
        int col = nd0 + nt * 8 + (t & 3) * 2;
        O[col * HW + q0 + r0]            = oacc[0][nt][0] * rl00;
        O[(col + 1) * HW + q0 + r0]      = oacc[0][nt][1] * rl00;
        O[col * HW + q0 + r0 + 8]        = oacc[0][nt][2] * rl01;
        O[(col + 1) * HW + q0 + r0 + 8]  = oacc[0][nt][3] * rl01;
        O[col * HW + q0 + r0 + 16]       = oacc[1][nt][0] * rl10;
        O[(col + 1) * HW + q0 + r0 + 16] = oacc[1][nt][1] * rl10;
        O[col * HW + q0 + r0 + 24]       = oacc[1][nt][2] * rl11;
        O[(col + 1) * HW + q0 + r0 + 24] = oacc[1][nt][3] * rl11;
    }
}

extern "C" void kernel_launch(void* const* d_in, const int* in_sizes, int n_in,
                              void* d_out, int out_size)
{
    const float* fea_left  = (const float*)d_in[0];
    const float* fea_right = (const float*)d_in[1];
    const float* Wq    = (const float*)d_in[2];
    const float* bq    = (const float*)d_in[3];
    const float* gq    = (const float*)d_in[4];
    const float* betaq = (const float*)d_in[5];
    const float* mq    = (const float*)d_in[6];
    const float* vq    = (const float*)d_in[7];
    const float* Wk    = (const float*)d_in[8];
    const float* bk    = (const float*)d_in[9];
    const float* gk    = (const float*)d_in[10];
    const float* betak = (const float*)d_in[11];
    const float* mk    = (const float*)d_in[12];
    const float* vk    = (const float*)d_in[13];
    float* out = (float*)d_out;

    vconv_kernel<<<(Bsz * CHW / 4 + 255) / 256, 256>>>(fea_left, fea_right);

    cudaFuncSetAttribute(proj_kernel, cudaFuncAttributeMaxDynamicSharedMemorySize, PJ_SMEM);
    proj_kernel<<<dim3(18, 2, 32), 256, PJ_SMEM>>>(fea_left, fea_right,
        Wq, bq, gq, betaq, mq, vq, Wk, bk, gk, betak, mk, vk);

    cudaFuncSetAttribute(attn_kernel, cudaFuncAttributeMaxDynamicSharedMemorySize, ATT_SMEM);
    attn_kernel<<<dim3(18, 16), 256, ATT_SMEM>>>(out);
}